// round 6
// baseline (speedup 1.0000x reference)
#include <cuda_runtime.h>
#include <cuda_bf16.h>
#include <math.h>
#include <stdint.h>

// Problem constants
#define BQ   16
#define CDIM 256
#define HW   64
#define NQ   65536
#define KCODES 1024
#define ZQ_ELEMS 16777216

#define MARGIN 0.0095f      // rigorous bf16 screen bound (2*2^-8 = 0.0078) + slack
#define CAND_CAP 8

// Screen tiling
#define MTILE 128           // queries per CTA
#define NCH   64            // codes per chunk
#define NCHUNKS (KCODES / NCH)
#define KSTEPS  (CDIM / 16)

// Padded smem pitch: 264 bf16 = 528 B (132 words ≡ 4 mod 32 banks -> ldmatrix conflict-free)
#define PITCH 528
#define SM_A  0
#define SM_B  (MTILE * PITCH)                    // 67584
#define SM_CNT (SM_B + NCH * PITCH)              // 101376
#define SM_CAND (SM_CNT + 512)                   // 101888
#define SM_TOTAL (SM_CAND + MTILE * CAND_CAP * 4) // 105984

// Scratch
__device__ float          g_zf[NQ * CDIM];
__device__ __nv_bfloat16  g_zfh[NQ * CDIM];
__device__ float          g_wn[KCODES * CDIM];
__device__ __nv_bfloat16  g_wnh[KCODES * CDIM];
__device__ float          g_wn2[KCODES];
__device__ float          g_en[KCODES];
__device__ float          g_en2[KCODES];
__device__ int            g_bi[NQ];
__device__ float          g_bd[NQ];
__device__ int            g_ncand[NQ];
__device__ int            g_cand[NQ * CAND_CAP];
__device__ double         g_loss;

__device__ __forceinline__ uint32_t smem_u32(const void* p) {
    uint32_t a;
    asm("{ .reg .u64 t; cvta.to.shared.u64 t, %1; cvt.u32.u64 %0, t; }" : "=r"(a) : "l"(p));
    return a;
}

__device__ __forceinline__ void ldmx4(uint32_t* r, uint32_t addr) {
    asm volatile("ldmatrix.sync.aligned.m8n8.x4.shared.b16 {%0,%1,%2,%3}, [%4];"
                 : "=r"(r[0]), "=r"(r[1]), "=r"(r[2]), "=r"(r[3]) : "r"(addr));
}

__device__ __forceinline__ void mma16816(float* d, const uint32_t* a, const uint32_t* b) {
    asm volatile(
        "mma.sync.aligned.m16n8k16.row.col.f32.bf16.bf16.f32 "
        "{%0,%1,%2,%3}, {%4,%5,%6,%7}, {%8,%9}, {%0,%1,%2,%3};"
        : "+f"(d[0]), "+f"(d[1]), "+f"(d[2]), "+f"(d[3])
        : "r"(a[0]), "r"(a[1]), "r"(a[2]), "r"(a[3]), "r"(b[0]), "r"(b[1]));
}

// ---------------------------------------------------------------------------
// Kernel A: normalize embedding rows (ref-emulating), norms, bf16 copy
// ---------------------------------------------------------------------------
__global__ void k_prep(const float* __restrict__ emb) {
    int k = blockIdx.x, t = threadIdx.x;
    if (k == 0 && t == 0) g_loss = 0.0;

    __shared__ double red[256];
    float v = emb[k * CDIM + t];
    red[t] = (double)v * (double)v;
    __syncthreads();
    #pragma unroll
    for (int s = 128; s > 0; s >>= 1) { if (t < s) red[t] += red[t + s]; __syncthreads(); }
    __shared__ float sDen;
    if (t == 0) {
        float n2 = (float)red[0];
        float n  = sqrtf(n2);
        float den = fmaxf(n, 1e-12f);
        g_en[k] = den; g_en2[k] = n2; sDen = den;
    }
    __syncthreads();
    float wn = v / sDen;
    g_wn[k * CDIM + t]  = wn;
    g_wnh[k * CDIM + t] = __float2bfloat16(wn);

    red[t] = (double)wn * (double)wn;
    __syncthreads();
    #pragma unroll
    for (int s = 128; s > 0; s >>= 1) { if (t < s) red[t] += red[t + s]; __syncthreads(); }
    if (t == 0) g_wn2[k] = (float)red[0];
}

// ---------------------------------------------------------------------------
// Kernel B: normalize z along W (ref-emulating), transpose -> zf [N,C] fp32+bf16
// ---------------------------------------------------------------------------
__global__ void k_znorm(const float* __restrict__ z) {
    __shared__ float tile[64][65];
    __shared__ float den[64];
    int bh = blockIdx.x;
    int b = bh >> 6, h = bh & 63;
    int t = threadIdx.x;
    long n0 = (long)bh * 64;

    for (int c0 = 0; c0 < CDIM; c0 += 64) {
        for (int i = t; i < 4096; i += 256) {
            int r = i >> 6, w = i & 63;
            tile[r][w] = z[(((long)b * CDIM + (c0 + r)) * HW + h) * HW + w];
        }
        __syncthreads();
        if (t < 64) {
            double s = 0.0;
            #pragma unroll
            for (int w = 0; w < 64; w++) { double v = (double)tile[t][w]; s += v * v; }
            den[t] = fmaxf(sqrtf((float)s), 1e-12f);
        }
        __syncthreads();
        for (int i = t; i < 4096; i += 256) {
            int w = i >> 6, cc = i & 63;
            float val = tile[cc][w] / den[cc];
            long o = (n0 + w) * CDIM + c0 + cc;
            g_zf[o]  = val;
            g_zfh[o] = __float2bfloat16(val);
        }
        __syncthreads();
    }
}

// ---------------------------------------------------------------------------
// Kernel C: bf16 HMMA screen. 512 CTAs x 256 threads (8 warps), 2 CTAs/SM.
// Warp w owns query rows 16w..16w+15; chunk = 64 codes; K=256 via 16 ksteps.
// Per kstep: 1 ldmatrix.x4 (A) + 4 ldmatrix.x4 (B, 2 n8-frags each) + 8 HMMA.
// Epilogue: per-quad argmax over D frags + margin candidate collection.
// ---------------------------------------------------------------------------
__global__ void __launch_bounds__(256, 2) k_screen() {
    extern __shared__ char sm[];
    const int t = threadIdx.x;
    const int w = t >> 5, lane = t & 31;
    const int g = lane >> 2, tig = lane & 3;
    const int n0 = blockIdx.x * MTILE;

    int* s_cnt  = (int*)(sm + SM_CNT);
    int* s_cand = (int*)(sm + SM_CAND);
    if (t < MTILE) s_cnt[t] = 0;

    // Load A tile: 128 rows x 256 bf16 into padded rows
    {
        const uint4* src = (const uint4*)(g_zfh + (size_t)n0 * CDIM);
        #pragma unroll
        for (int i = 0; i < 16; i++) {
            int u = t + i * 256;
            *(uint4*)(sm + SM_A + (u >> 5) * PITCH + (u & 31) * 16) = src[u];
        }
    }
    __syncthreads();

    const uint32_t smb = smem_u32(sm);
    // A ldmatrix lane address: rows 16w + (lane&15); k-half (+8 elems = +16B) from lane>>4
    const uint32_t aAddr = smb + SM_A + (16 * w + (lane & 15)) * PITCH + (lane >> 4) * 16;
    // B ldmatrix lane address (x4 covers n8-frag pair f): row n = ((lane>>4)<<3)+(lane&7),
    // k-half (+16B) from bit 3
    const uint32_t bAddr = smb + SM_B + ((((lane >> 4) << 3) + (lane & 7)) * PITCH)
                           + (((lane >> 3) & 1) * 16);

    const int rowA = 16 * w + g;
    const int rowB = rowA + 8;
    float runA = -3.0e38f, runB = -3.0e38f;
    int   idxA = 0,        idxB = 0;

    for (int ch = 0; ch < NCHUNKS; ch++) {
        if (ch) __syncthreads();                 // all warps done with prev B
        {
            const uint4* src = (const uint4*)(g_wnh + (size_t)(ch * NCH) * CDIM);
            #pragma unroll
            for (int i = 0; i < 8; i++) {
                int u = t + i * 256;
                *(uint4*)(sm + SM_B + (u >> 5) * PITCH + (u & 31) * 16) = src[u];
            }
        }
        __syncthreads();

        float acc[8][4];
        #pragma unroll
        for (int nf = 0; nf < 8; nf++)
            #pragma unroll
            for (int j = 0; j < 4; j++) acc[nf][j] = 0.0f;

        #pragma unroll
        for (int s = 0; s < KSTEPS; s++) {
            uint32_t a[4];
            ldmx4(a, aAddr + s * 32);
            #pragma unroll
            for (int f = 0; f < 4; f++) {
                uint32_t b[4];
                ldmx4(b, bAddr + f * (16 * PITCH) + s * 32);
                mma16816(acc[2 * f],     a, b);
                mma16816(acc[2 * f + 1], a, b + 2);
            }
        }

        // ---- epilogue: chunk argmax ----
        const int cb = ch * NCH;
        float bA = -3.0e38f, bB = -3.0e38f;
        int   iA = 0,        iB = 0;
        #pragma unroll
        for (int nf = 0; nf < 8; nf++) {
            #pragma unroll
            for (int jj = 0; jj < 2; jj++) {
                int col = cb + nf * 8 + 2 * tig + jj;
                float v0 = acc[nf][jj];
                if (v0 > bA) { bA = v0; iA = col; }
                float v1 = acc[nf][2 + jj];
                if (v1 > bB) { bB = v1; iB = col; }
            }
        }
        #pragma unroll
        for (int off = 1; off <= 2; off <<= 1) {
            float ov = __shfl_xor_sync(0xFFFFFFFFu, bA, off);
            int   oi = __shfl_xor_sync(0xFFFFFFFFu, iA, off);
            if (ov > bA || (ov == bA && oi < iA)) { bA = ov; iA = oi; }
            ov = __shfl_xor_sync(0xFFFFFFFFu, bB, off);
            oi = __shfl_xor_sync(0xFFFFFFFFu, iB, off);
            if (ov > bB || (ov == bB && oi < iB)) { bB = ov; iB = oi; }
        }
        if (bA > runA) { runA = bA; idxA = iA; }
        if (bB > runB) { runB = bB; idxB = iB; }

        // ---- margin candidates vs running best (superset-safe) ----
        const float thrA = runA - MARGIN, thrB = runB - MARGIN;
        #pragma unroll
        for (int nf = 0; nf < 8; nf++) {
            #pragma unroll
            for (int jj = 0; jj < 2; jj++) {
                int col = cb + nf * 8 + 2 * tig + jj;
                if (acc[nf][jj] >= thrA) {
                    int p = atomicAdd(&s_cnt[rowA], 1);
                    if (p < CAND_CAP) s_cand[rowA * CAND_CAP + p] = col;
                }
                if (acc[nf][2 + jj] >= thrB) {
                    int p = atomicAdd(&s_cnt[rowB], 1);
                    if (p < CAND_CAP) s_cand[rowB * CAND_CAP + p] = col;
                }
            }
        }
    }

    __syncthreads();
    if (tig == 0) {
        int nA = n0 + rowA, nB = n0 + rowB;
        g_bi[nA] = idxA; g_bd[nA] = runA;
        g_bi[nB] = idxB; g_bd[nB] = runB;
        int cA = s_cnt[rowA]; g_ncand[nA] = cA;
        int mA = cA < CAND_CAP ? cA : CAND_CAP;
        for (int c = 0; c < mA; c++) g_cand[nA * CAND_CAP + c] = s_cand[rowA * CAND_CAP + c];
        int cB = s_cnt[rowB]; g_ncand[nB] = cB;
        int mB = cB < CAND_CAP ? cB : CAND_CAP;
        for (int c = 0; c < mB; c++) g_cand[nB * CAND_CAP + c] = s_cand[rowB * CAND_CAP + c];
    }
}

// ---------------------------------------------------------------------------
// Kernel C2: exact re-ranking (fp64), emulating reference arithmetic.
// ---------------------------------------------------------------------------
__global__ void k_refine(float* __restrict__ out_idx) {
    int warp = (blockIdx.x * blockDim.x + threadIdx.x) >> 5;
    int lane = threadIdx.x & 31;
    __shared__ double s_loss;
    if (threadIdx.x == 0) s_loss = 0.0;
    __syncthreads();

    if (warp < NQ) {
        int n = warp;
        int cnt = g_ncand[n];
        int bi; float bd;
        if (cnt <= 1) {
            bi = g_bi[n]; bd = g_bd[n];
        } else {
            float zr[8];
            #pragma unroll
            for (int m = 0; m < 8; m++) zr[m] = g_zf[(long)n * CDIM + lane + 32 * m];
            double z2 = 0.0;
            #pragma unroll
            for (int m = 0; m < 8; m++) z2 += (double)zr[m] * (double)zr[m];
            #pragma unroll
            for (int off = 16; off > 0; off >>= 1)
                z2 += __shfl_xor_sync(0xFFFFFFFFu, z2, off);
            float zf2f = (float)z2;

            bool overflow = (cnt > CAND_CAP);
            int ncand = overflow ? KCODES : cnt;
            float dmin = 3.4e38f; int kmin = 0x7FFFFFFF; float bestdot = 0.0f;
            for (int ci = 0; ci < ncand; ci++) {
                int k = overflow ? ci : g_cand[n * CAND_CAP + ci];
                double dot = 0.0;
                const float* wrow = g_wn + (long)k * CDIM;
                #pragma unroll
                for (int m = 0; m < 8; m++)
                    dot += (double)zr[m] * (double)wrow[lane + 32 * m];
                #pragma unroll
                for (int off = 16; off > 0; off >>= 1)
                    dot += __shfl_xor_sync(0xFFFFFFFFu, dot, off);
                float dotf = (float)dot;
                float d = (zf2f + g_wn2[k]) - 2.0f * dotf;
                if (d < dmin || (d == dmin && k < kmin)) { dmin = d; kmin = k; bestdot = dotf; }
            }
            bi = kmin; bd = bestdot;
        }
        if (lane == 0) {
            g_bi[n] = bi;
            out_idx[n] = (float)bi;
            atomicAdd(&s_loss, (double)g_en2[bi] - 2.0 * (double)bd * (double)g_en[bi]);
        }
    }
    __syncthreads();
    if (threadIdx.x == 0) atomicAdd(&g_loss, s_loss);
}

// ---------------------------------------------------------------------------
// Kernel D: gather z_q = embedding[idx], transpose back to [B,C,H,W]
// ---------------------------------------------------------------------------
__global__ void k_gather(const float* __restrict__ emb, float* __restrict__ out) {
    __shared__ int   sIdx[64];
    __shared__ float es[64][129];
    int bh = blockIdx.x;
    int b = bh >> 6, h = bh & 63;
    int t = threadIdx.x;
    long n0 = (long)bh * 64;

    if (t < 64) sIdx[t] = g_bi[n0 + t];
    __syncthreads();

    for (int c0 = 0; c0 < CDIM; c0 += 128) {
        for (int i = t; i < 64 * 128; i += 256) {
            int s = i >> 7, cc = i & 127;
            es[s][cc] = emb[(long)sIdx[s] * CDIM + c0 + cc];
        }
        __syncthreads();
        for (int i = t; i < 64 * 128; i += 256) {
            int cc = i >> 6, w = i & 63;
            out[(((long)b * CDIM + (c0 + cc)) * HW + h) * HW + w] = es[w][cc];
        }
        __syncthreads();
    }
}

// ---------------------------------------------------------------------------
// Kernel E: finalize loss. Sum_n ||zf_n||^2 == 262144 exactly.
// ---------------------------------------------------------------------------
__global__ void k_loss(float* __restrict__ out_loss) {
    double S = g_loss + 262144.0;
    out_loss[0] = (float)(1.25 * S / (double)ZQ_ELEMS);
}

// ---------------------------------------------------------------------------
extern "C" void kernel_launch(void* const* d_in, const int* in_sizes, int n_in,
                              void* d_out, int out_size) {
    const float* z   = (const float*)d_in[0];
    const float* emb = (const float*)d_in[1];
    float* out = (float*)d_out;

    cudaFuncSetAttribute(k_screen, cudaFuncAttributeMaxDynamicSharedMemorySize, SM_TOTAL);

    k_prep<<<KCODES, 256>>>(emb);
    k_znorm<<<BQ * HW, 256>>>(z);
    k_screen<<<NQ / MTILE, 256, SM_TOTAL>>>();
    k_refine<<<NQ / 8, 256>>>(out + ZQ_ELEMS);
    k_gather<<<BQ * HW, 256>>>(emb, out);
    k_loss<<<1, 1>>>(out + ZQ_ELEMS + NQ);
}

// round 7
// speedup vs baseline: 1.4758x; 1.4758x over previous
#include <cuda_runtime.h>
#include <math.h>
#include <stdint.h>

// Problem constants
#define BQ   16
#define CDIM 256
#define HW   64
#define NQ   65536
#define KCODES 1024
#define ZQ_ELEMS 16777216

#define MARGIN 1e-3f
#define CAND_CAP 8

// GEMM tiling
#define MT  128
#define NTC 128
#define KT  16

typedef unsigned long long u64;

// Scratch
__device__ float  g_zf [NQ * CDIM];      // [N][C] fp32 (refine row access)
__device__ float  g_zfT[CDIM * NQ];      // [C][N] fp32 (GEMM A, k-major rows)
__device__ float  g_wn [KCODES * CDIM];  // [K][C] fp32 (refine)
__device__ float  g_wnT[CDIM * KCODES];  // [C][K] fp32 (GEMM B)
__device__ float  g_wn2[KCODES];
__device__ float  g_en [KCODES];
__device__ float  g_en2[KCODES];
__device__ int    g_bi[NQ];
__device__ float  g_bd[NQ];
__device__ int    g_ncand[NQ];
__device__ int    g_cand[NQ * CAND_CAP];
__device__ double g_loss;

// ---- f32x2 helpers (Blackwell packed fp32: 2x FFMA throughput) ----
__device__ __forceinline__ u64 pack_dup(float a) {
    u64 r; asm("mov.b64 %0, {%1, %1};" : "=l"(r) : "f"(a)); return r;
}
__device__ __forceinline__ void ffma2(u64& d, u64 a, u64 b) {
    asm("fma.rn.f32x2 %0, %1, %2, %0;" : "+l"(d) : "l"(a), "l"(b));
}
__device__ __forceinline__ float2 unpk(u64 v) {
    float2 f; asm("mov.b64 {%0, %1}, %2;" : "=f"(f.x), "=f"(f.y) : "l"(v)); return f;
}

// ---------------------------------------------------------------------------
// Kernel A: normalize embedding rows (ref-emulating), norms, transposed copy
// ---------------------------------------------------------------------------
__global__ void k_prep(const float* __restrict__ emb) {
    int k = blockIdx.x, t = threadIdx.x;
    if (k == 0 && t == 0) g_loss = 0.0;

    __shared__ double red[256];
    float v = emb[k * CDIM + t];
    red[t] = (double)v * (double)v;
    __syncthreads();
    #pragma unroll
    for (int s = 128; s > 0; s >>= 1) { if (t < s) red[t] += red[t + s]; __syncthreads(); }
    __shared__ float sDen;
    if (t == 0) {
        float n2 = (float)red[0];
        float n  = sqrtf(n2);
        float den = fmaxf(n, 1e-12f);
        g_en[k] = den; g_en2[k] = n2; sDen = den;
    }
    __syncthreads();
    float wn = v / sDen;
    g_wn [k * CDIM + t] = wn;
    g_wnT[t * KCODES + k] = wn;

    red[t] = (double)wn * (double)wn;
    __syncthreads();
    #pragma unroll
    for (int s = 128; s > 0; s >>= 1) { if (t < s) red[t] += red[t + s]; __syncthreads(); }
    if (t == 0) g_wn2[k] = (float)red[0];
}

// ---------------------------------------------------------------------------
// Kernel B: normalize z along W (ref-emulating), write zf [N][C] and zfT [C][N]
// ---------------------------------------------------------------------------
__global__ void k_znorm(const float* __restrict__ z) {
    __shared__ float tile[64][65];
    __shared__ float den[64];
    int bh = blockIdx.x;
    int b = bh >> 6, h = bh & 63;
    int t = threadIdx.x;
    long n0 = (long)bh * 64;

    for (int c0 = 0; c0 < CDIM; c0 += 64) {
        for (int i = t; i < 4096; i += 256) {
            int r = i >> 6, w = i & 63;
            tile[r][w] = z[(((long)b * CDIM + (c0 + r)) * HW + h) * HW + w];
        }
        __syncthreads();
        if (t < 64) {
            double s = 0.0;
            #pragma unroll
            for (int w = 0; w < 64; w++) { double v = (double)tile[t][w]; s += v * v; }
            den[t] = fmaxf(sqrtf((float)s), 1e-12f);
        }
        __syncthreads();
        // zf [N][C]: coalesced in cc
        for (int i = t; i < 4096; i += 256) {
            int w = i >> 6, cc = i & 63;
            g_zf[(n0 + w) * CDIM + c0 + cc] = tile[cc][w] / den[cc];
        }
        // zfT [C][N]: coalesced in w
        for (int i = t; i < 4096; i += 256) {
            int cc = i >> 6, w = i & 63;
            g_zfT[(long)(c0 + cc) * NQ + n0 + w] = tile[cc][w] / den[cc];
        }
        __syncthreads();
    }
}

// ---------------------------------------------------------------------------
// Kernel C: fp32x2 GEMM screen (D = zf * wn^T) + argmax + margin candidates.
// 512 blocks x 256 threads, 2 CTAs/SM. Block: 128 q x (8 chunks of 128 codes)
// x K=256 (16 k-tiles). Thread: 8x8 microtile as 8x4 f32x2 accumulators.
// Operands pre-transposed -> contiguous float4 tile fills (no scatter STS).
// ---------------------------------------------------------------------------
__global__ void __launch_bounds__(256, 2) k_gemm_argmax() {
    __shared__ float As[2][KT][MT];
    __shared__ float Bs[2][KT][NTC];
    __shared__ float s_bv[MT];
    __shared__ int   s_bi[MT];
    __shared__ int   s_cnt[MT];
    __shared__ int   s_cand[MT][CAND_CAP];

    const int t  = threadIdx.x;
    const int tx = t & 15;          // code-dim coord (8 cols = 4 f32x2)
    const int ty = t >> 4;          // query-dim coord (8 rows)
    const int n0 = blockIdx.x * MT;

    if (t < MT) { s_bv[t] = -3.0e38f; s_bi[t] = 0; s_cnt[t] = 0; }
    __syncthreads();

    // tile fill coords: 512 float4 per tile, 2 per thread (contiguous)
    const int kr0 = t >> 4,  c40 = (t & 15) * 4;            // u = t       (rows 0..15)
    const int kr1 = kr0;                                    // u = t + 256 -> same k rows? no:
    // u0 = t: k = t>>5 (0..7), col4 = t&31 ; u1 = t+256: k = 8 + (t>>5)
    const int ka0 = t >> 5,       ca0 = (t & 31) * 4;
    const int ka1 = (t >> 5) + 8, ca1 = (t & 31) * 4;
    (void)kr0; (void)kr1; (void)c40;

    for (int ch = 0; ch < 8; ch++) {
        const int code0 = ch * NTC;

        u64 acc[8][4];
        #pragma unroll
        for (int i = 0; i < 8; i++)
            #pragma unroll
            for (int j = 0; j < 4; j++) acc[i][j] = 0ull;

        // prologue: k-tile 0 -> buffer 0
        {
            float4 a0 = *(const float4*)(g_zfT + (long)ka0 * NQ + n0 + ca0);
            float4 a1 = *(const float4*)(g_zfT + (long)ka1 * NQ + n0 + ca1);
            float4 b0 = *(const float4*)(g_wnT + (long)ka0 * KCODES + code0 + ca0);
            float4 b1 = *(const float4*)(g_wnT + (long)ka1 * KCODES + code0 + ca1);
            *(float4*)&As[0][ka0][ca0] = a0;
            *(float4*)&As[0][ka1][ca1] = a1;
            *(float4*)&Bs[0][ka0][ca0] = b0;
            *(float4*)&Bs[0][ka1][ca1] = b1;
        }
        __syncthreads();

        for (int kt = 0; kt < CDIM / KT; kt++) {
            const int cur = kt & 1;
            float4 na0, na1, nb0, nb1;
            if (kt < CDIM / KT - 1) {
                const int k0 = (kt + 1) * KT;
                na0 = *(const float4*)(g_zfT + (long)(k0 + ka0) * NQ + n0 + ca0);
                na1 = *(const float4*)(g_zfT + (long)(k0 + ka1) * NQ + n0 + ca1);
                nb0 = *(const float4*)(g_wnT + (long)(k0 + ka0) * KCODES + code0 + ca0);
                nb1 = *(const float4*)(g_wnT + (long)(k0 + ka1) * KCODES + code0 + ca1);
            }
            #pragma unroll
            for (int k = 0; k < KT; k++) {
                u64 b2[4];
                #pragma unroll
                for (int j = 0; j < 4; j++)
                    b2[j] = *(const u64*)&Bs[cur][k][tx * 8 + 2 * j];
                #pragma unroll
                for (int i = 0; i < 8; i++) {
                    u64 a2 = pack_dup(As[cur][k][ty * 8 + i]);
                    #pragma unroll
                    for (int j = 0; j < 4; j++)
                        ffma2(acc[i][j], a2, b2[j]);
                }
            }
            if (kt < CDIM / KT - 1) {
                const int nxt = cur ^ 1;
                *(float4*)&As[nxt][ka0][ca0] = na0;
                *(float4*)&As[nxt][ka1][ca1] = na1;
                *(float4*)&Bs[nxt][ka0][ca0] = nb0;
                *(float4*)&Bs[nxt][ka1][ca1] = nb1;
            }
            __syncthreads();
        }

        // ---- chunk argmax (cols of acc[i][j]: lo=tx*8+2j, hi=tx*8+2j+1) ----
        #pragma unroll
        for (int i = 0; i < 8; i++) {
            float bv = -3.0e38f;
            int   bj = 0;
            #pragma unroll
            for (int j = 0; j < 4; j++) {
                float2 p = unpk(acc[i][j]);
                if (p.x > bv) { bv = p.x; bj = 2 * j; }
                if (p.y > bv) { bv = p.y; bj = 2 * j + 1; }
            }
            int bc = code0 + tx * 8 + bj;
            #pragma unroll
            for (int off = 8; off > 0; off >>= 1) {
                float ov = __shfl_xor_sync(0xFFFFFFFFu, bv, off, 16);
                int   oc = __shfl_xor_sync(0xFFFFFFFFu, bc, off, 16);
                if (ov > bv || (ov == bv && oc < bc)) { bv = ov; bc = oc; }
            }
            if (tx == 0) {
                int row = ty * 8 + i;
                if (bv > s_bv[row]) { s_bv[row] = bv; s_bi[row] = bc; }
            }
        }

        // ---- margin candidates vs running best (stale-read is superset-safe) ----
        #pragma unroll
        for (int i = 0; i < 8; i++) {
            int row = ty * 8 + i;
            float thr = s_bv[row] - MARGIN;
            #pragma unroll
            for (int j = 0; j < 4; j++) {
                float2 p = unpk(acc[i][j]);
                if (p.x >= thr) {
                    int pos = atomicAdd(&s_cnt[row], 1);
                    if (pos < CAND_CAP) s_cand[row][pos] = code0 + tx * 8 + 2 * j;
                }
                if (p.y >= thr) {
                    int pos = atomicAdd(&s_cnt[row], 1);
                    if (pos < CAND_CAP) s_cand[row][pos] = code0 + tx * 8 + 2 * j + 1;
                }
            }
        }
        __syncthreads();
    }

    if (t < MT) {
        int n = n0 + t;
        g_bi[n] = s_bi[t];
        g_bd[n] = s_bv[t];
        int cnt = s_cnt[t];
        g_ncand[n] = cnt;
        int m = cnt < CAND_CAP ? cnt : CAND_CAP;
        for (int c = 0; c < m; c++) g_cand[n * CAND_CAP + c] = s_cand[t][c];
    }
}

// ---------------------------------------------------------------------------
// Kernel C2: exact re-ranking (fp64), emulating reference arithmetic.
// ---------------------------------------------------------------------------
__global__ void k_refine(float* __restrict__ out_idx) {
    int warp = (blockIdx.x * blockDim.x + threadIdx.x) >> 5;
    int lane = threadIdx.x & 31;
    __shared__ double s_loss;
    if (threadIdx.x == 0) s_loss = 0.0;
    __syncthreads();

    if (warp < NQ) {
        int n = warp;
        int cnt = g_ncand[n];
        int bi; float bd;
        if (cnt <= 1) {
            bi = g_bi[n]; bd = g_bd[n];
        } else {
            float zr[8];
            #pragma unroll
            for (int m = 0; m < 8; m++) zr[m] = g_zf[(long)n * CDIM + lane + 32 * m];
            double z2 = 0.0;
            #pragma unroll
            for (int m = 0; m < 8; m++) z2 += (double)zr[m] * (double)zr[m];
            #pragma unroll
            for (int off = 16; off > 0; off >>= 1)
                z2 += __shfl_xor_sync(0xFFFFFFFFu, z2, off);
            float zf2f = (float)z2;

            bool overflow = (cnt > CAND_CAP);
            int ncand = overflow ? KCODES : cnt;
            float dmin = 3.4e38f; int kmin = 0x7FFFFFFF; float bestdot = 0.0f;
            for (int ci = 0; ci < ncand; ci++) {
                int k = overflow ? ci : g_cand[n * CAND_CAP + ci];
                double dot = 0.0;
                const float* wrow = g_wn + (long)k * CDIM;
                #pragma unroll
                for (int m = 0; m < 8; m++)
                    dot += (double)zr[m] * (double)wrow[lane + 32 * m];
                #pragma unroll
                for (int off = 16; off > 0; off >>= 1)
                    dot += __shfl_xor_sync(0xFFFFFFFFu, dot, off);
                float dotf = (float)dot;
                float d = (zf2f + g_wn2[k]) - 2.0f * dotf;
                if (d < dmin || (d == dmin && k < kmin)) { dmin = d; kmin = k; bestdot = dotf; }
            }
            bi = kmin; bd = bestdot;
        }
        if (lane == 0) {
            g_bi[n] = bi;
            out_idx[n] = (float)bi;
            atomicAdd(&s_loss, (double)g_en2[bi] - 2.0 * (double)bd * (double)g_en[bi]);
        }
    }
    __syncthreads();
    if (threadIdx.x == 0) atomicAdd(&g_loss, s_loss);
}

// ---------------------------------------------------------------------------
// Kernel D: gather z_q = embedding[idx], transpose back to [B,C,H,W]
// ---------------------------------------------------------------------------
__global__ void k_gather(const float* __restrict__ emb, float* __restrict__ out) {
    __shared__ int   sIdx[64];
    __shared__ float es[64][129];
    int bh = blockIdx.x;
    int b = bh >> 6, h = bh & 63;
    int t = threadIdx.x;
    long n0 = (long)bh * 64;

    if (t < 64) sIdx[t] = g_bi[n0 + t];
    __syncthreads();

    for (int c0 = 0; c0 < CDIM; c0 += 128) {
        for (int i = t; i < 64 * 128; i += 256) {
            int s = i >> 7, cc = i & 127;
            es[s][cc] = emb[(long)sIdx[s] * CDIM + c0 + cc];
        }
        __syncthreads();
        for (int i = t; i < 64 * 128; i += 256) {
            int cc = i >> 6, w = i & 63;
            out[(((long)b * CDIM + (c0 + cc)) * HW + h) * HW + w] = es[w][cc];
        }
        __syncthreads();
    }
}

// ---------------------------------------------------------------------------
// Kernel E: finalize loss. Sum_n ||zf_n||^2 == 262144 exactly.
// ---------------------------------------------------------------------------
__global__ void k_loss(float* __restrict__ out_loss) {
    double S = g_loss + 262144.0;
    out_loss[0] = (float)(1.25 * S / (double)ZQ_ELEMS);
}

// ---------------------------------------------------------------------------
extern "C" void kernel_launch(void* const* d_in, const int* in_sizes, int n_in,
                              void* d_out, int out_size) {
    const float* z   = (const float*)d_in[0];
    const float* emb = (const float*)d_in[1];
    float* out = (float*)d_out;

    k_prep<<<KCODES, 256>>>(emb);
    k_znorm<<<BQ * HW, 256>>>(z);
    k_gemm_argmax<<<NQ / MT, 256>>>();
    k_refine<<<NQ / 8, 256>>>(out + ZQ_ELEMS);
    k_gather<<<BQ * HW, 256>>>(emb, out);
    k_loss<<<1, 1>>>(out + ZQ_ELEMS + NQ);
}